// round 4
// baseline (speedup 1.0000x reference)
#include <cuda_runtime.h>

#define NB 32
#define NC 192
#define NL 4096

// Scratch (no dynamic allocation allowed)
__device__ int   g_order[NB * NL];
__device__ int   g_count[NB];
__device__ float g_theta[NB];

// ---------------------------------------------------------------------------
// Kernel 1: per-batch stats (min/max, mean/std of normalized |delta|) +
// stable stream-compaction index build via block prefix sum.
// 1 block per batch, 1024 threads, 4 elements/thread (float4 load).
// ---------------------------------------------------------------------------
__global__ __launch_bounds__(1024) void stats_scan_kernel(const float* __restrict__ delta)
{
    const int b    = blockIdx.x;
    const int tid  = threadIdx.x;
    const int lane = tid & 31;
    const int warp = tid >> 5;

    __shared__ float  smn[32], smx[32];
    __shared__ double ssum[32], ssq[32];
    __shared__ int    wsum[32];
    __shared__ float  stheta;

    float4 v = reinterpret_cast<const float4*>(delta + (size_t)b * NL)[tid];
    float a0 = fabsf(v.x), a1 = fabsf(v.y), a2 = fabsf(v.z), a3 = fabsf(v.w);

    float mn = fminf(fminf(a0, a1), fminf(a2, a3));
    float mx = fmaxf(fmaxf(a0, a1), fmaxf(a2, a3));
    #pragma unroll
    for (int o = 16; o; o >>= 1) {
        mn = fminf(mn, __shfl_xor_sync(0xffffffffu, mn, o));
        mx = fmaxf(mx, __shfl_xor_sync(0xffffffffu, mx, o));
    }
    if (lane == 0) { smn[warp] = mn; smx[warp] = mx; }
    __syncthreads();
    if (warp == 0) {
        mn = smn[lane]; mx = smx[lane];
        #pragma unroll
        for (int o = 16; o; o >>= 1) {
            mn = fminf(mn, __shfl_xor_sync(0xffffffffu, mn, o));
            mx = fmaxf(mx, __shfl_xor_sync(0xffffffffu, mx, o));
        }
        if (lane == 0) { smn[0] = mn; smx[0] = mx; }
    }
    __syncthreads();

    const float lo  = smn[0];
    const float rng = fmaxf(smx[0] - lo, 1e-3f);

    // Normalized importance, fp32 element-wise exactly as the reference
    float i0 = (a0 - lo) / rng;
    float i1 = (a1 - lo) / rng;
    float i2 = (a2 - lo) / rng;
    float i3 = (a3 - lo) / rng;

    double s = (double)i0 + (double)i1 + (double)i2 + (double)i3;
    double q = (double)i0 * i0 + (double)i1 * i1 + (double)i2 * i2 + (double)i3 * i3;
    #pragma unroll
    for (int o = 16; o; o >>= 1) {
        s += __shfl_xor_sync(0xffffffffu, s, o);
        q += __shfl_xor_sync(0xffffffffu, q, o);
    }
    if (lane == 0) { ssum[warp] = s; ssq[warp] = q; }
    __syncthreads();
    if (warp == 0) {
        s = ssum[lane]; q = ssq[lane];
        #pragma unroll
        for (int o = 16; o; o >>= 1) {
            s += __shfl_xor_sync(0xffffffffu, s, o);
            q += __shfl_xor_sync(0xffffffffu, q, o);
        }
        if (lane == 0) {
            double mu  = s / (double)NL;
            double var = (q - s * s / (double)NL) / (double)(NL - 1);
            if (var < 0.0) var = 0.0;
            stheta = (float)(mu - 0.1 * sqrt(var));
        }
    }
    __syncthreads();

    const float theta = stheta;

    // keep flags (stable order: thread tid owns tokens [4*tid, 4*tid+3])
    int k0 = (i0 >= theta) ? 1 : 0;
    int k1 = (i1 >= theta) ? 1 : 0;
    int k2 = (i2 >= theta) ? 1 : 0;
    int k3 = (i3 >= theta) ? 1 : 0;
    int local = k0 + k1 + k2 + k3;

    // block-wide exclusive prefix sum over per-thread keep counts
    int incl = local;
    #pragma unroll
    for (int o = 1; o < 32; o <<= 1) {
        int t = __shfl_up_sync(0xffffffffu, incl, o);
        if (lane >= o) incl += t;
    }
    if (lane == 31) wsum[warp] = incl;
    __syncthreads();
    if (warp == 0) {
        int t = wsum[lane];
        #pragma unroll
        for (int o = 1; o < 32; o <<= 1) {
            int u = __shfl_up_sync(0xffffffffu, t, o);
            if (lane >= o) t += u;
        }
        wsum[lane] = t;  // inclusive scan of warp totals
    }
    __syncthreads();

    int pos  = (warp ? wsum[warp - 1] : 0) + (incl - local);
    int base = b * NL;
    int l    = tid * 4;
    if (k0) g_order[base + pos++] = l;
    if (k1) g_order[base + pos++] = l + 1;
    if (k2) g_order[base + pos++] = l + 2;
    if (k3) g_order[base + pos++] = l + 3;

    // zero-fill the tail so the gather kernel reads benign indices
    int cnt_total = wsum[31];
    for (int j = cnt_total + tid; j < NL; j += 1024) g_order[base + j] = 0;

    if (tid == 0) {
        g_count[b] = cnt_total;
        g_theta[b] = theta;
    }
}

// ---------------------------------------------------------------------------
// Kernel 2: gather. One block per (b, c) pair; 1024 threads x float4 = 4096.
// Coalesced float4 store; monotonic gathered reads; order table L2-resident.
// ---------------------------------------------------------------------------
__global__ __launch_bounds__(1024) void gather_kernel(const float* __restrict__ x,
                                                      float* __restrict__ y)
{
    const int bc  = blockIdx.x;          // b*NC + c
    const int b   = bc / NC;
    const int tid = threadIdx.x;

    const int cnt = g_count[b];
    const int4 o  = reinterpret_cast<const int4*>(g_order + b * NL)[tid];

    const float* xb = x + (size_t)bc * NL;
    const int j = tid * 4;

    float4 r;
    r.x = (j     < cnt) ? __ldg(xb + o.x) : 0.0f;
    r.y = (j + 1 < cnt) ? __ldg(xb + o.y) : 0.0f;
    r.z = (j + 2 < cnt) ? __ldg(xb + o.z) : 0.0f;
    r.w = (j + 3 < cnt) ? __ldg(xb + o.w) : 0.0f;

    reinterpret_cast<float4*>(y + (size_t)bc * NL)[tid] = r;
}

// ---------------------------------------------------------------------------
// Kernel 3: scalar outputs. keep_ratio = mean(counts)/L ; theta_mean.
// ---------------------------------------------------------------------------
__global__ void finalize_kernel(float* __restrict__ out_kr, float* __restrict__ out_tm)
{
    const int t = threadIdx.x;  // 32 threads
    float cnt = (float)g_count[t];
    float th  = g_theta[t];
    #pragma unroll
    for (int o = 16; o; o >>= 1) {
        cnt += __shfl_xor_sync(0xffffffffu, cnt, o);
        th  += __shfl_xor_sync(0xffffffffu, th,  o);
    }
    if (t == 0) {
        *out_kr = (cnt / (float)NB) / (float)NL;
        *out_tm = th / (float)NB;
    }
}

extern "C" void kernel_launch(void* const* d_in, const int* in_sizes, int n_in,
                              void* d_out, int out_size)
{
    const float* x     = (const float*)d_in[0];   // [32,192,64,64]
    const float* delta = (const float*)d_in[1];   // [32,1,64,64]
    float* out = (float*)d_out;

    stats_scan_kernel<<<NB, 1024>>>(delta);
    gather_kernel<<<NB * NC, 1024>>>(x, out);
    finalize_kernel<<<1, 32>>>(out + (out_size - 2), out + (out_size - 1));
}

// round 5
// speedup vs baseline: 1.0252x; 1.0252x over previous
#include <cuda_runtime.h>

#define NB  32
#define NC  192
#define NL  4096
#define CPB 2                 // channels per gather block
#define GBLK (NB * NC / CPB)  // 3072 gather blocks

// Scratch (no dynamic allocation allowed)
__device__ int   g_order[NB * NL];
__device__ int   g_count[NB];
__device__ float g_theta[NB];

// ---------------------------------------------------------------------------
// Kernel 1: per-batch single-pass stats + stable compaction index build.
// 32 blocks x 256 threads, 16 contiguous elements per thread.
// min/max/sum/sumsq over raw |delta| in ONE reduction; theta derived:
//   mu_imp = (mean_a - lo)/rng,  sigma_imp = sigma_a/rng   (affine identity)
// Keep test uses per-element fp32 imp exactly as the reference.
// ---------------------------------------------------------------------------
__global__ __launch_bounds__(256) void stats_scan_kernel(const float* __restrict__ delta)
{
    const int b    = blockIdx.x;
    const int tid  = threadIdx.x;
    const int lane = tid & 31;
    const int warp = tid >> 5;   // 8 warps

    __shared__ float  smn[8], smx[8];
    __shared__ double ssum[8], ssq[8];
    __shared__ int    wsum[8];
    __shared__ float  s_lo, s_rng, s_theta;

    // thread owns contiguous tokens [16*tid, 16*tid+16)
    const float4* dp = reinterpret_cast<const float4*>(delta + (size_t)b * NL) + tid * 4;
    float a[16];
    #pragma unroll
    for (int i = 0; i < 4; i++) {
        float4 v = dp[i];
        a[4*i+0] = fabsf(v.x); a[4*i+1] = fabsf(v.y);
        a[4*i+2] = fabsf(v.z); a[4*i+3] = fabsf(v.w);
    }

    float mn = a[0], mx = a[0];
    double s = 0.0, q = 0.0;
    #pragma unroll
    for (int i = 0; i < 16; i++) {
        mn = fminf(mn, a[i]); mx = fmaxf(mx, a[i]);
        double d = (double)a[i];
        s += d; q += d * d;
    }

    #pragma unroll
    for (int o = 16; o; o >>= 1) {
        mn = fminf(mn, __shfl_xor_sync(0xffffffffu, mn, o));
        mx = fmaxf(mx, __shfl_xor_sync(0xffffffffu, mx, o));
        s += __shfl_xor_sync(0xffffffffu, s, o);
        q += __shfl_xor_sync(0xffffffffu, q, o);
    }
    if (lane == 0) { smn[warp] = mn; smx[warp] = mx; ssum[warp] = s; ssq[warp] = q; }
    __syncthreads();

    if (warp == 0 && lane < 8) {
        mn = smn[lane]; mx = smx[lane]; s = ssum[lane]; q = ssq[lane];
        #pragma unroll
        for (int o = 4; o; o >>= 1) {
            mn = fminf(mn, __shfl_xor_sync(0xffu, mn, o));
            mx = fmaxf(mx, __shfl_xor_sync(0xffu, mx, o));
            s += __shfl_xor_sync(0xffu, s, o);
            q += __shfl_xor_sync(0xffu, q, o);
        }
        if (lane == 0) {
            float lo  = mn;
            float rng = fmaxf(mx - lo, 1e-3f);
            double mu_a  = s / (double)NL;
            double var_a = (q - s * s / (double)NL) / (double)(NL - 1);
            if (var_a < 0.0) var_a = 0.0;
            double mu_imp = (mu_a - (double)lo) / (double)rng;
            double sg_imp = sqrt(var_a) / (double)rng;
            s_lo = lo; s_rng = rng;
            s_theta = (float)(mu_imp - 0.1 * sg_imp);
        }
    }
    __syncthreads();

    const float lo = s_lo, rng = s_rng, theta = s_theta;

    // keep flags (per-element fp32 imp, matching reference arithmetic)
    unsigned kbits = 0;
    int local = 0;
    #pragma unroll
    for (int i = 0; i < 16; i++) {
        float imp = (a[i] - lo) / rng;
        if (imp >= theta) { kbits |= (1u << i); local++; }
    }

    // block-wide prefix: warp scan of per-thread counts, then warp totals
    int incl = local;
    #pragma unroll
    for (int o = 1; o < 32; o <<= 1) {
        int t = __shfl_up_sync(0xffffffffu, incl, o);
        if (lane >= o) incl += t;
    }
    if (lane == 31) wsum[warp] = incl;
    __syncthreads();
    if (warp == 0 && lane < 8) {
        int t = wsum[lane];
        #pragma unroll
        for (int o = 1; o < 8; o <<= 1) {
            int u = __shfl_up_sync(0xffu, t, o);
            if (lane >= o) t += u;
        }
        wsum[lane] = t;  // inclusive scan of 8 warp totals
    }
    __syncthreads();

    int pos  = (warp ? wsum[warp - 1] : 0) + (incl - local);
    int base = b * NL;
    int l    = tid * 16;
    #pragma unroll
    for (int i = 0; i < 16; i++) {
        if (kbits & (1u << i)) g_order[base + pos++] = l + i;
    }

    int cnt_total = wsum[7];
    // zero-fill tail so gather reads benign indices
    for (int j = cnt_total + tid; j < NL; j += 256) g_order[base + j] = 0;

    if (tid == 0) {
        g_count[b] = cnt_total;
        g_theta[b] = theta;
    }
}

// ---------------------------------------------------------------------------
// Kernel 2: gather. One block per (b, 2 channels); 512 threads.
// Rows staged in SMEM via LDG.128 (coalesced), order int4s loaded once and
// reused for both channels (halves order-table L2 traffic), compacted output
// via SMEM gather with coalesced float4 stores. Block 0 also emits scalars.
// ---------------------------------------------------------------------------
__global__ __launch_bounds__(512) void gather_kernel(const float* __restrict__ x,
                                                     float* __restrict__ y,
                                                     float* __restrict__ out_kr,
                                                     float* __restrict__ out_tm)
{
    __shared__ float sx[CPB * NL];   // 32 KB

    const int blk = blockIdx.x;                  // 0..GBLK-1
    const int tid = threadIdx.x;
    const int b   = blk / (NC / CPB);
    const int c0  = (blk % (NC / CPB)) * CPB;
    const size_t base = ((size_t)b * NC + c0) * NL;

    // stage CPB rows: CPB*NL floats = 2048 float4, 512 threads -> 4 each
    const float4* xp = reinterpret_cast<const float4*>(x + base);
    #pragma unroll
    for (int i = 0; i < CPB * NL / 4 / 512; i++)
        reinterpret_cast<float4*>(sx)[tid + 512 * i] = xp[tid + 512 * i];

    const int4* op = reinterpret_cast<const int4*>(g_order + b * NL);
    const int4 o0 = op[2 * tid];
    const int4 o1 = op[2 * tid + 1];
    const int  cnt = g_count[b];
    __syncthreads();

    const int j = 8 * tid;
    float4* yp = reinterpret_cast<float4*>(y + base);
    #pragma unroll
    for (int r = 0; r < CPB; r++) {
        const float* sr = sx + r * NL;
        float4 r0, r1;
        r0.x = (j     < cnt) ? sr[o0.x] : 0.0f;
        r0.y = (j + 1 < cnt) ? sr[o0.y] : 0.0f;
        r0.z = (j + 2 < cnt) ? sr[o0.z] : 0.0f;
        r0.w = (j + 3 < cnt) ? sr[o0.w] : 0.0f;
        r1.x = (j + 4 < cnt) ? sr[o1.x] : 0.0f;
        r1.y = (j + 5 < cnt) ? sr[o1.y] : 0.0f;
        r1.z = (j + 6 < cnt) ? sr[o1.z] : 0.0f;
        r1.w = (j + 7 < cnt) ? sr[o1.w] : 0.0f;
        yp[r * (NL / 4) + 2 * tid]     = r0;
        yp[r * (NL / 4) + 2 * tid + 1] = r1;
    }

    // scalar outputs (g_count/g_theta finalized before this kernel launched)
    if (blk == 0 && tid < 32) {
        float cntf = (float)g_count[tid];
        float th   = g_theta[tid];
        #pragma unroll
        for (int o = 16; o; o >>= 1) {
            cntf += __shfl_xor_sync(0xffffffffu, cntf, o);
            th   += __shfl_xor_sync(0xffffffffu, th,   o);
        }
        if (tid == 0) {
            *out_kr = (cntf / (float)NB) / (float)NL;
            *out_tm = th / (float)NB;
        }
    }
}

extern "C" void kernel_launch(void* const* d_in, const int* in_sizes, int n_in,
                              void* d_out, int out_size)
{
    const float* x     = (const float*)d_in[0];   // [32,192,64,64]
    const float* delta = (const float*)d_in[1];   // [32,1,64,64]
    float* out = (float*)d_out;

    stats_scan_kernel<<<NB, 256>>>(delta);
    gather_kernel<<<GBLK, 512>>>(x, out,
                                 out + (out_size - 2), out + (out_size - 1));
}

// round 6
// speedup vs baseline: 1.1774x; 1.1485x over previous
#include <cuda_runtime.h>

#define NB  32
#define NC  192
#define NL  4096
#define CPB 2                 // channels per gather block
#define GBLK (NB * NC / CPB)  // 3072 gather blocks

// Scratch (no dynamic allocation allowed)
__device__ int   g_order[NB * NL];
__device__ int   g_count[NB];
__device__ float g_theta[NB];

__device__ __forceinline__ void pdl_trigger() {
    asm volatile("griddepcontrol.launch_dependents;" ::: "memory");
}
__device__ __forceinline__ void pdl_wait() {
    asm volatile("griddepcontrol.wait;" ::: "memory");
}

// ---------------------------------------------------------------------------
// Kernel 1: per-batch single-pass stats + stable compaction index build.
// 32 blocks x 256 threads, 16 contiguous elements per thread.
// Triggers programmatic launch of the gather kernel at entry so gather's
// x-staging overlaps with this kernel's latency.
// ---------------------------------------------------------------------------
__global__ __launch_bounds__(256) void stats_scan_kernel(const float* __restrict__ delta)
{
    pdl_trigger();   // let the gather kernel start staging x immediately

    const int b    = blockIdx.x;
    const int tid  = threadIdx.x;
    const int lane = tid & 31;
    const int warp = tid >> 5;   // 8 warps

    __shared__ float  smn[8], smx[8];
    __shared__ double ssum[8], ssq[8];
    __shared__ int    wsum[8];
    __shared__ float  s_lo, s_rng, s_theta;

    // thread owns contiguous tokens [16*tid, 16*tid+16)
    const float4* dp = reinterpret_cast<const float4*>(delta + (size_t)b * NL) + tid * 4;
    float a[16];
    #pragma unroll
    for (int i = 0; i < 4; i++) {
        float4 v = dp[i];
        a[4*i+0] = fabsf(v.x); a[4*i+1] = fabsf(v.y);
        a[4*i+2] = fabsf(v.z); a[4*i+3] = fabsf(v.w);
    }

    float mn = a[0], mx = a[0];
    double s = 0.0, q = 0.0;
    #pragma unroll
    for (int i = 0; i < 16; i++) {
        mn = fminf(mn, a[i]); mx = fmaxf(mx, a[i]);
        double d = (double)a[i];
        s += d; q += d * d;
    }

    #pragma unroll
    for (int o = 16; o; o >>= 1) {
        mn = fminf(mn, __shfl_xor_sync(0xffffffffu, mn, o));
        mx = fmaxf(mx, __shfl_xor_sync(0xffffffffu, mx, o));
        s += __shfl_xor_sync(0xffffffffu, s, o);
        q += __shfl_xor_sync(0xffffffffu, q, o);
    }
    if (lane == 0) { smn[warp] = mn; smx[warp] = mx; ssum[warp] = s; ssq[warp] = q; }
    __syncthreads();

    if (warp == 0 && lane < 8) {
        mn = smn[lane]; mx = smx[lane]; s = ssum[lane]; q = ssq[lane];
        #pragma unroll
        for (int o = 4; o; o >>= 1) {
            mn = fminf(mn, __shfl_xor_sync(0xffu, mn, o));
            mx = fmaxf(mx, __shfl_xor_sync(0xffu, mx, o));
            s += __shfl_xor_sync(0xffu, s, o);
            q += __shfl_xor_sync(0xffu, q, o);
        }
        if (lane == 0) {
            float lo  = mn;
            float rng = fmaxf(mx - lo, 1e-3f);
            double mu_a  = s / (double)NL;
            double var_a = (q - s * s / (double)NL) / (double)(NL - 1);
            if (var_a < 0.0) var_a = 0.0;
            double mu_imp = (mu_a - (double)lo) / (double)rng;
            double sg_imp = sqrt(var_a) / (double)rng;
            s_lo = lo; s_rng = rng;
            s_theta = (float)(mu_imp - 0.1 * sg_imp);
        }
    }
    __syncthreads();

    const float lo = s_lo, rng = s_rng, theta = s_theta;

    // keep flags (per-element fp32 imp, matching reference arithmetic)
    unsigned kbits = 0;
    int local = 0;
    #pragma unroll
    for (int i = 0; i < 16; i++) {
        float imp = (a[i] - lo) / rng;
        if (imp >= theta) { kbits |= (1u << i); local++; }
    }

    // block-wide prefix: warp scan of per-thread counts, then warp totals
    int incl = local;
    #pragma unroll
    for (int o = 1; o < 32; o <<= 1) {
        int t = __shfl_up_sync(0xffffffffu, incl, o);
        if (lane >= o) incl += t;
    }
    if (lane == 31) wsum[warp] = incl;
    __syncthreads();
    if (warp == 0 && lane < 8) {
        int t = wsum[lane];
        #pragma unroll
        for (int o = 1; o < 8; o <<= 1) {
            int u = __shfl_up_sync(0xffu, t, o);
            if (lane >= o) t += u;
        }
        wsum[lane] = t;  // inclusive scan of 8 warp totals
    }
    __syncthreads();

    int pos  = (warp ? wsum[warp - 1] : 0) + (incl - local);
    int base = b * NL;
    int l    = tid * 16;
    #pragma unroll
    for (int i = 0; i < 16; i++) {
        if (kbits & (1u << i)) g_order[base + pos++] = l + i;
    }

    int cnt_total = wsum[7];
    // zero-fill tail so gather reads benign indices
    for (int j = cnt_total + tid; j < NL; j += 256) g_order[base + j] = 0;

    if (tid == 0) {
        g_count[b] = cnt_total;
        g_theta[b] = theta;
    }
}

// ---------------------------------------------------------------------------
// Kernel 2: gather. One block per (b, 2 channels); 512 threads.
// Launched with programmatic stream serialization: starts while stats runs,
// stages x rows to SMEM (independent of stats), then griddepcontrol.wait
// before consuming g_order / g_count / g_theta.
// ---------------------------------------------------------------------------
__global__ __launch_bounds__(512) void gather_kernel(const float* __restrict__ x,
                                                     float* __restrict__ y,
                                                     float* __restrict__ out_kr,
                                                     float* __restrict__ out_tm)
{
    __shared__ float sx[CPB * NL];   // 32 KB

    const int blk = blockIdx.x;                  // 0..GBLK-1
    const int tid = threadIdx.x;
    const int b   = blk / (NC / CPB);
    const int c0  = (blk % (NC / CPB)) * CPB;
    const size_t base = ((size_t)b * NC + c0) * NL;

    // stage CPB rows: CPB*NL floats = 2048 float4, 512 threads -> 4 each
    // (independent of the stats kernel's output -> overlaps with it)
    const float4* xp = reinterpret_cast<const float4*>(x + base);
    #pragma unroll
    for (int i = 0; i < CPB * NL / 4 / 512; i++)
        reinterpret_cast<float4*>(sx)[tid + 512 * i] = xp[tid + 512 * i];

    // wait for stats kernel completion (memory visibility of g_* writes)
    pdl_wait();

    const int4* op = reinterpret_cast<const int4*>(g_order + b * NL);
    const int4 o0 = op[2 * tid];
    const int4 o1 = op[2 * tid + 1];
    const int  cnt = g_count[b];
    __syncthreads();

    const int j = 8 * tid;
    float4* yp = reinterpret_cast<float4*>(y + base);
    #pragma unroll
    for (int r = 0; r < CPB; r++) {
        const float* sr = sx + r * NL;
        float4 r0, r1;
        r0.x = (j     < cnt) ? sr[o0.x] : 0.0f;
        r0.y = (j + 1 < cnt) ? sr[o0.y] : 0.0f;
        r0.z = (j + 2 < cnt) ? sr[o0.z] : 0.0f;
        r0.w = (j + 3 < cnt) ? sr[o0.w] : 0.0f;
        r1.x = (j + 4 < cnt) ? sr[o1.x] : 0.0f;
        r1.y = (j + 5 < cnt) ? sr[o1.y] : 0.0f;
        r1.z = (j + 6 < cnt) ? sr[o1.z] : 0.0f;
        r1.w = (j + 7 < cnt) ? sr[o1.w] : 0.0f;
        yp[r * (NL / 4) + 2 * tid]     = r0;
        yp[r * (NL / 4) + 2 * tid + 1] = r1;
    }

    // scalar outputs (g_count/g_theta visible after pdl_wait)
    if (blk == 0 && tid < 32) {
        float cntf = (float)g_count[tid];
        float th   = g_theta[tid];
        #pragma unroll
        for (int o = 16; o; o >>= 1) {
            cntf += __shfl_xor_sync(0xffffffffu, cntf, o);
            th   += __shfl_xor_sync(0xffffffffu, th,   o);
        }
        if (tid == 0) {
            *out_kr = (cntf / (float)NB) / (float)NL;
            *out_tm = th / (float)NB;
        }
    }
}

extern "C" void kernel_launch(void* const* d_in, const int* in_sizes, int n_in,
                              void* d_out, int out_size)
{
    const float* x     = (const float*)d_in[0];   // [32,192,64,64]
    const float* delta = (const float*)d_in[1];   // [32,1,64,64]
    float* out = (float*)d_out;

    stats_scan_kernel<<<NB, 256>>>(delta);

    cudaLaunchConfig_t cfg = {};
    cfg.gridDim  = dim3(GBLK, 1, 1);
    cfg.blockDim = dim3(512, 1, 1);
    cfg.dynamicSmemBytes = 0;
    cfg.stream = 0;
    cudaLaunchAttribute attr[1];
    attr[0].id = cudaLaunchAttributeProgrammaticStreamSerialization;
    attr[0].val.programmaticStreamSerializationAllowed = 1;
    cfg.attrs = attr;
    cfg.numAttrs = 1;
    cudaLaunchKernelEx(&cfg, gather_kernel, x, out,
                       out + (out_size - 2), out + (out_size - 1));
}